// round 8
// baseline (speedup 1.0000x reference)
#include <cuda_runtime.h>
#include <math.h>

#define BB 512
#define SS 1024
#define TT 52
#define START_TAG 50
#define END_TAG 51
#define LOG2E 1.4426950408889634f
#define LN2 0.6931471805599453

typedef unsigned long long ull;

// ---------------- device scratch (no allocations allowed) ----------------
__device__ __align__(16) float g_E[TT * TT];   // exp(transitions)
__device__ int    g_len[BB];
__device__ int    g_isU8;
__device__ __align__(8) float g_alpha[BB][64];
__device__ __align__(8) float g_beta[BB][64];
__device__ int    g_Ka[BB], g_Kb[BB];
__device__ float  g_m0[BB];
__device__ double g_goldp[BB][4];

__device__ double g_final[BB];

// ---------------- packed f32x2 helpers (Blackwell) ----------------
__device__ __forceinline__ ull f2pack(float lo, float hi) {
    ull r;
    asm("mov.b64 %0, {%1, %2};" : "=l"(r) : "f"(lo), "f"(hi));
    return r;
}
__device__ __forceinline__ float2 f2unpack(ull a) {
    float2 r;
    asm("mov.b64 {%0, %1}, %2;" : "=f"(r.x), "=f"(r.y) : "l"(a));
    return r;
}
__device__ __forceinline__ float f2lo(ull a) {
    float r;
    asm("{ .reg .b32 hi; mov.b64 {%0, hi}, %1; }" : "=f"(r) : "l"(a));
    return r;
}
__device__ __forceinline__ ull f2fma(ull a, ull b, ull c) {
    ull d;
    asm("fma.rn.f32x2 %0, %1, %2, %3;" : "=l"(d) : "l"(a), "l"(b), "l"(c));
    return d;
}
__device__ __forceinline__ ull f2mul(ull a, ull b) {
    ull d;
    asm("mul.rn.f32x2 %0, %1, %2;" : "=l"(d) : "l"(a), "l"(b));
    return d;
}
__device__ __forceinline__ ull f2add(ull a, ull b) {
    ull d;
    asm("add.rn.f32x2 %0, %1, %2;" : "=l"(d) : "l"(a), "l"(b));
    return d;
}
__device__ __forceinline__ float ex2(float x) {
    float y;
    asm("ex2.approx.ftz.f32 %0, %1;" : "=f"(y) : "f"(x));
    return y;
}

// matvec: u = sum over 26 packed i-pairs of q (in qv) times Ep, 4 accums
__device__ __forceinline__ float matvec26(const ulonglong2* qv, const ull* Ep) {
    ull a0 = f2mul(qv[0].x, Ep[0]);
    ull a1 = f2mul(qv[0].y, Ep[1]);
    ull a2 = f2mul(qv[1].x, Ep[2]);
    ull a3 = f2mul(qv[1].y, Ep[3]);
    #pragma unroll
    for (int c = 2; c < 13; c++) {
        if (c & 1) {
            a2 = f2fma(qv[c].x, Ep[2 * c],     a2);
            a3 = f2fma(qv[c].y, Ep[2 * c + 1], a3);
        } else {
            a0 = f2fma(qv[c].x, Ep[2 * c],     a0);
            a1 = f2fma(qv[c].y, Ep[2 * c + 1], a1);
        }
    }
    a0 = f2add(a0, a2);
    a1 = f2add(a1, a3);
    a0 = f2add(a0, a1);
    float2 h = f2unpack(a0);
    return h.x + h.y;
}

// ---------------- mask dtype detection + E table ----------------
// Under any 4-byte 0/1 encoding (int32 bool or float32 0.0/1.0) the byte at
// offset b*SS+1 is always 0; under uint8 it's mask[b][1], nonzero w.h.p.
__global__ void k_detect(const void* mask, const float* __restrict__ tr) {
    int tid = threadIdx.x;     // 256
    if (tid < 32) {
        const unsigned char* p = (const unsigned char*)mask;
        int any = 0;
        for (int b = tid; b < BB; b += 32)
            any |= (int)p[(size_t)b * SS + 1];
        #pragma unroll
        for (int o = 16; o; o >>= 1) any |= __shfl_xor_sync(0xffffffffu, any, o);
        if (tid == 0) g_isU8 = (any != 0);
    }
    for (int idx = tid; idx < TT * TT; idx += 256)
        g_E[idx] = expf(tr[idx]);
}

// ---------------- gold partials: one thread per (b, s) -------------------
// Grid 2048, block 256: cta -> (b = cta>>2, chunk c = cta&3), s = c*256+tid.
// Maximal MLP: every thread issues its 4-5 independent loads at once.
// END-transition term is added later in k_combine (needs len).
__global__ void k_gold2(const void* mask,
                        const float* __restrict__ feats,
                        const int* __restrict__ tags,
                        const float* __restrict__ tr) {
    int b   = blockIdx.x >> 2;
    int c   = blockIdx.x & 3;
    int tid = threadIdx.x;       // 256
    int s   = (c << 8) + tid;
    __shared__ double sg[8];

    bool on;
    if (g_isU8) on = ((const unsigned char*)mask)[(size_t)b * SS + s] != 0;
    else        on = ((const unsigned int*)mask)[(size_t)b * SS + s] != 0;

    double term = 0.0;
    if (on) {
        const int* tg = tags + (size_t)b * SS;
        int tag  = tg[s];
        int prev = (s == 0) ? START_TAG : tg[s - 1];
        term = (double)feats[((size_t)b * SS + s) * TT + tag]
             + (double)tr[prev * TT + tag];
    }
    #pragma unroll
    for (int o = 16; o; o >>= 1) term += __shfl_xor_sync(0xffffffffu, term, o);
    if ((tid & 31) == 0) sg[tid >> 5] = term;
    __syncthreads();
    if (tid == 0) {
        double acc = 0.0;
        #pragma unroll
        for (int i = 0; i < 8; i++) acc += sg[i];
        g_goldp[b][c] = acc;
    }
}

// ---------------- forward/backward scan, single-warp CTAs ----------------
// CTA 0..511: forward alpha over s=0..m; CTA 512..1023: backward beta over
// s=len-1..m, m=(len-1)/2. Thread t<26 owns tag pair (2t, 2t+1); the 13
// LDS.128 q-loads are shared by both matvecs. Length is self-computed in a
// short prologue (no separate length kernel; fwd CTA publishes g_len[b]).
__global__ void __launch_bounds__(32, 1) k_main(const void* mask,
                                                const float* __restrict__ feats,
                                                const float* __restrict__ tr) {
    const int cta = blockIdx.x;
    const int b = cta & (BB - 1);
    const bool isFwd = cta < BB;
    const int t = threadIdx.x;            // 0..31
    const bool act = (t < 26);
    const int tcl = act ? t : 25;
    const int jA = act ? 2 * t : 50;
    const int jB = act ? 2 * t + 1 : 51;
    __shared__ __align__(16) float shq[2][64];

    // ---- self-computed length (warp scan of mask row b) ----
    int cnt = 0;
    if (g_isU8) {
        const uint4* p = (const uint4*)((const unsigned char*)mask + (size_t)b * SS);
        #pragma unroll
        for (int r = 0; r < 2; r++) {          // 1024 B = 64 uint4
            uint4 w = p[t + 32 * r];
            cnt += __popc(__vsetgtu4(w.x, 0u)) + __popc(__vsetgtu4(w.y, 0u))
                 + __popc(__vsetgtu4(w.z, 0u)) + __popc(__vsetgtu4(w.w, 0u));
        }
    } else {
        const uint4* p = (const uint4*)((const unsigned int*)mask + (size_t)b * SS);
        #pragma unroll
        for (int r = 0; r < 8; r++) {          // 4096 B = 256 uint4
            uint4 w = p[t + 32 * r];
            cnt += (w.x != 0) + (w.y != 0) + (w.z != 0) + (w.w != 0);
        }
    }
    #pragma unroll
    for (int o = 16; o; o >>= 1) cnt += __shfl_xor_sync(0xffffffffu, cnt, o);
    const int len = cnt;
    if (isFwd && t == 0) g_len[b] = len;      // for k_combine

    const int m = (len - 1) >> 1;
    const float* fb = feats + (size_t)b * SS * TT;
    const ull L2E2 = f2pack(LOG2E, LOG2E);

    if (isFwd) {
        const int L = m + 1;              // steps s=1..m
        // E columns jA, jB packed over i-pairs
        ull EpA[26], EpB[26];
        #pragma unroll
        for (int c = 0; c < 26; c++) {
            EpA[c] = f2pack(g_E[(2 * c) * TT + jA], g_E[(2 * c + 1) * TT + jA]);
            EpB[c] = f2pack(g_E[(2 * c) * TT + jB], g_E[(2 * c + 1) * TT + jB]);
        }

        // init: part0 = feats[b,0,:] + trans[START,:]
        float p0A = act ? (fb[jA] + tr[START_TAG * TT + jA]) : -1e30f;
        float p0B = act ? (fb[jB] + tr[START_TAG * TT + jB]) : -1e30f;
        float mx = fmaxf(p0A, p0B);
        #pragma unroll
        for (int o = 16; o; o >>= 1)
            mx = fmaxf(mx, __shfl_xor_sync(0xffffffffu, mx, o));
        const float m0 = mx;
        float uA = act ? ex2((p0A - m0) * LOG2E) : 0.0f;
        float uB = act ? ex2((p0B - m0) * LOG2E) : 0.0f;
        ((float2*)shq[0])[t] = make_float2(uA, uB);
        int Ktot = 0;
        __syncwarp();

        // emission pair prefetch (distance 4), pre-scaled by log2e
        const float2* pe = (const float2*)fb + tcl;   // stride 26 float2/step
        ull fl0 = 0, fl1 = 0, fl2 = 0, fl3 = 0;
        if (1 < L) { float2 v = pe[1 * 26]; fl0 = f2mul(f2pack(v.x, v.y), L2E2); }
        if (2 < L) { float2 v = pe[2 * 26]; fl1 = f2mul(f2pack(v.x, v.y), L2E2); }
        if (3 < L) { float2 v = pe[3 * 26]; fl2 = f2mul(f2pack(v.x, v.y), L2E2); }
        if (4 < L) { float2 v = pe[4 * 26]; fl3 = f2mul(f2pack(v.x, v.y), L2E2); }

        for (int s = 1; s < L; s++) {
            float2 fc = f2unpack(fl0);
            float efA = ex2(fc.x), efB = ex2(fc.y);
            fl0 = fl1; fl1 = fl2; fl2 = fl3;
            int sp = s + 4;
            float2 nv = make_float2(0.f, 0.f);
            if (sp < L) nv = pe[sp * 26];
            fl3 = f2mul(f2pack(nv.x, nv.y), L2E2);

            const ulonglong2* q8 = (const ulonglong2*)shq[(s - 1) & 1];
            ulonglong2 qv[13];
            #pragma unroll
            for (int c = 0; c < 13; c++) qv[c] = q8[c];

            float q0 = f2lo(qv[0].x);
            int ex = ((__float_as_int(q0) >> 23) & 0xFF) - 127;
            Ktot += ex;
            float scale = __int_as_float((127 - ex) << 23);
            float preA = scale * efA, preB = scale * efB;

            uA = matvec26(qv, EpA) * preA;
            uB = matvec26(qv, EpB) * preB;

            float2 st = act ? make_float2(uA, uB) : make_float2(0.f, 0.f);
            ((float2*)shq[s & 1])[t] = st;
            __syncwarp();
        }
        if (act) ((float2*)g_alpha[b])[t] = make_float2(uA, uB);
        if (t == 0) { g_Ka[b] = Ktot; g_m0[b] = m0; }
    } else {
        const int N = len - 1 - m;        // iterations: s = len-2 .. m
        // E rows jA, jB packed over column-pairs (contiguous 8B loads)
        ull EpA[26], EpB[26];
        const ull* ErA = (const ull*)(g_E + jA * TT);
        const ull* ErB = (const ull*)(g_E + jB * TT);
        #pragma unroll
        for (int c = 0; c < 26; c++) { EpA[c] = ErA[c]; EpB[c] = ErB[c]; }

        float EendA = g_E[jA * TT + END_TAG];
        float EendB = g_E[jB * TT + END_TAG];
        float uA, uB;
        if (len >= 2) {
            const float* fl = fb + (size_t)(len - 1) * TT;
            uA = ex2(fl[jA] * LOG2E) * EendA;
            uB = ex2(fl[jB] * LOG2E) * EendB;
        } else {
            uA = EendA; uB = EendB;       // len==1: beta = E[:,END], no ef
        }
        if (!act) { uA = 0.f; uB = 0.f; }
        ((float2*)shq[0])[t] = make_float2(uA, uB);
        int Ktot = 0;
        __syncwarp();

        // emission f_s needed only for iterations k <= N-2 (ef==1 at s==m)
        const float2* pb = (const float2*)fb + tcl;
        ull fl0 = 0, fl1 = 0, fl2 = 0, fl3 = 0;
        if (N >= 2) { float2 v = pb[(size_t)(len - 2) * 26]; fl0 = f2mul(f2pack(v.x, v.y), L2E2); }
        if (N >= 3) { float2 v = pb[(size_t)(len - 3) * 26]; fl1 = f2mul(f2pack(v.x, v.y), L2E2); }
        if (N >= 4) { float2 v = pb[(size_t)(len - 4) * 26]; fl2 = f2mul(f2pack(v.x, v.y), L2E2); }
        if (N >= 5) { float2 v = pb[(size_t)(len - 5) * 26]; fl3 = f2mul(f2pack(v.x, v.y), L2E2); }

        for (int k = 0; k < N; k++) {
            float2 fc = f2unpack(fl0);
            float efA = ex2(fc.x), efB = ex2(fc.y);
            fl0 = fl1; fl1 = fl2; fl2 = fl3;
            int kk = k + 4;
            float2 nv = make_float2(0.f, 0.f);
            if (kk <= N - 2) nv = pb[(size_t)(len - 2 - kk) * 26];
            fl3 = f2mul(f2pack(nv.x, nv.y), L2E2);

            const ulonglong2* q8 = (const ulonglong2*)shq[k & 1];
            ulonglong2 qv[13];
            #pragma unroll
            for (int c = 0; c < 13; c++) qv[c] = q8[c];

            float q0 = f2lo(qv[0].x);
            int ex = ((__float_as_int(q0) >> 23) & 0xFF) - 127;
            Ktot += ex;
            float scale = __int_as_float((127 - ex) << 23);
            float preA = scale * efA, preB = scale * efB;

            uA = matvec26(qv, EpA) * preA;
            uB = matvec26(qv, EpB) * preB;

            float2 st = act ? make_float2(uA, uB) : make_float2(0.f, 0.f);
            ((float2*)shq[(k + 1) & 1])[t] = st;
            __syncwarp();
        }
        if (act) ((float2*)g_beta[b])[t] = make_float2(uA, uB);
        if (t == 0) g_Kb[b] = Ktot;
    }
}

// ---------------- combine: logZ_b - gold_b (incl. END term) --------------
__global__ void k_combine(const int* __restrict__ tags,
                          const float* __restrict__ tr) {
    int b = blockIdx.x;
    int l = threadIdx.x;   // 32
    double d = (double)g_alpha[b][l] * (double)g_beta[b][l];
    if (l < TT - 32)
        d += (double)g_alpha[b][l + 32] * (double)g_beta[b][l + 32];
    #pragma unroll
    for (int o = 16; o; o >>= 1) d += __shfl_xor_sync(0xffffffffu, d, o);
    if (l == 0) {
        double gold = g_goldp[b][0] + g_goldp[b][1]
                    + g_goldp[b][2] + g_goldp[b][3];
        int len = g_len[b];
        int etag = tags[(size_t)b * SS + len - 1];
        gold += (double)tr[etag * TT + END_TAG];
        double logZ = (double)g_m0[b] +
                      (double)(g_Ka[b] + g_Kb[b]) * LN2 + log(d);
        g_final[b] = logZ - gold;
    }
}

// ---------------- final reduction ----------------
__global__ void k_reduce(float* out) {
    __shared__ double sh[16];
    int tid = threadIdx.x;  // 512 threads
    double a = g_final[tid];
    #pragma unroll
    for (int o = 16; o; o >>= 1) a += __shfl_xor_sync(0xffffffffu, a, o);
    if ((tid & 31) == 0) sh[tid >> 5] = a;
    __syncthreads();
    if (tid < 32) {
        double v = (tid < 16) ? sh[tid] : 0.0;
        #pragma unroll
        for (int o = 8; o; o >>= 1) v += __shfl_xor_sync(0xffffffffu, v, o);
        if (tid == 0) out[0] = (float)v;
    }
}

// ---------------- launch ----------------
extern "C" void kernel_launch(void* const* d_in, const int* in_sizes, int n_in,
                              void* d_out, int out_size) {
    const float* feats = (const float*)d_in[0];
    const void*  mask  = d_in[1];
    const int*   tags  = (const int*)d_in[2];
    const float* tr    = (const float*)d_in[3];
    float* out = (float*)d_out;

    k_detect<<<1, 256>>>(mask, tr);
    k_gold2<<<4 * BB, 256>>>(mask, feats, tags, tr);
    k_main<<<2 * BB, 32>>>(mask, feats, tr);
    k_combine<<<BB, 32>>>(tags, tr);
    k_reduce<<<1, 512>>>(out);
}

// round 9
// speedup vs baseline: 1.5578x; 1.5578x over previous
#include <cuda_runtime.h>
#include <math.h>

#define BB 512
#define SS 1024
#define TT 52
#define START_TAG 50
#define END_TAG 51
#define LOG2E 1.4426950408889634f
#define LN2 0.6931471805599453

typedef unsigned long long ull;

// ---------------- device scratch (no allocations allowed) ----------------
__device__ __align__(16) float g_E[TT * TT];   // exp(transitions)
__device__ int    g_isU8;
__device__ __align__(16) int g_lenp[BB][4];    // per-chunk length partials
__device__ __align__(8) float g_alpha[BB][64];
__device__ __align__(8) float g_beta[BB][64];
__device__ int    g_Ka[BB], g_Kb[BB];
__device__ float  g_m0[BB];
__device__ double g_goldp[BB][4];              // per-chunk gold partials
__device__ double g_final[BB];

// ---------------- packed f32x2 helpers (Blackwell) ----------------
__device__ __forceinline__ ull f2pack(float lo, float hi) {
    ull r;
    asm("mov.b64 %0, {%1, %2};" : "=l"(r) : "f"(lo), "f"(hi));
    return r;
}
__device__ __forceinline__ float2 f2unpack(ull a) {
    float2 r;
    asm("mov.b64 {%0, %1}, %2;" : "=f"(r.x), "=f"(r.y) : "l"(a));
    return r;
}
__device__ __forceinline__ float f2lo(ull a) {
    float r;
    asm("{ .reg .b32 hi; mov.b64 {%0, hi}, %1; }" : "=f"(r) : "l"(a));
    return r;
}
__device__ __forceinline__ ull f2fma(ull a, ull b, ull c) {
    ull d;
    asm("fma.rn.f32x2 %0, %1, %2, %3;" : "=l"(d) : "l"(a), "l"(b), "l"(c));
    return d;
}
__device__ __forceinline__ ull f2mul(ull a, ull b) {
    ull d;
    asm("mul.rn.f32x2 %0, %1, %2;" : "=l"(d) : "l"(a), "l"(b));
    return d;
}
__device__ __forceinline__ ull f2add(ull a, ull b) {
    ull d;
    asm("add.rn.f32x2 %0, %1, %2;" : "=l"(d) : "l"(a), "l"(b));
    return d;
}
__device__ __forceinline__ float ex2(float x) {
    float y;
    asm("ex2.approx.ftz.f32 %0, %1;" : "=f"(y) : "f"(x));
    return y;
}

// matvec: u = sum over 26 packed i-pairs of q (in qv) times Ep, 4 accums
__device__ __forceinline__ float matvec26(const ulonglong2* qv, const ull* Ep) {
    ull a0 = f2mul(qv[0].x, Ep[0]);
    ull a1 = f2mul(qv[0].y, Ep[1]);
    ull a2 = f2mul(qv[1].x, Ep[2]);
    ull a3 = f2mul(qv[1].y, Ep[3]);
    #pragma unroll
    for (int c = 2; c < 13; c++) {
        if (c & 1) {
            a2 = f2fma(qv[c].x, Ep[2 * c],     a2);
            a3 = f2fma(qv[c].y, Ep[2 * c + 1], a3);
        } else {
            a0 = f2fma(qv[c].x, Ep[2 * c],     a0);
            a1 = f2fma(qv[c].y, Ep[2 * c + 1], a1);
        }
    }
    a0 = f2add(a0, a2);
    a1 = f2add(a1, a3);
    a0 = f2add(a0, a1);
    float2 h = f2unpack(a0);
    return h.x + h.y;
}

// ---------------- mask dtype detection + E table ----------------
// Under any 4-byte 0/1 encoding (int32 bool or float32 0.0/1.0) the byte at
// offset b*SS+1 is always 0; under uint8 it's mask[b][1], nonzero w.h.p.
__global__ void k_detect(const void* mask, const float* __restrict__ tr) {
    int tid = threadIdx.x;     // 256
    if (tid < 32) {
        const unsigned char* p = (const unsigned char*)mask;
        int any = 0;
        for (int b = tid; b < BB; b += 32)
            any |= (int)p[(size_t)b * SS + 1];
        #pragma unroll
        for (int o = 16; o; o >>= 1) any |= __shfl_xor_sync(0xffffffffu, any, o);
        if (tid == 0) g_isU8 = (any != 0);
    }
    for (int idx = tid; idx < TT * TT; idx += 256)
        g_E[idx] = expf(tr[idx]);
}

// ---------------- gold + length partials: one thread per (b, s) ----------
// Grid 2048, block 256: cta -> (b = cta>>2, chunk c = cta&3), s = c*256+tid.
// The thread owning the LAST valid position (mask[s] && !mask[s+1]) also
// adds the END-transition term, so k_combine needs no length/tags at all.
__global__ void k_gold2(const void* mask,
                        const float* __restrict__ feats,
                        const int* __restrict__ tags,
                        const float* __restrict__ tr) {
    int b   = blockIdx.x >> 2;
    int c   = blockIdx.x & 3;
    int tid = threadIdx.x;       // 256
    int s   = (c << 8) + tid;
    __shared__ double sg[8];
    __shared__ int    sc[8];

    bool on, onNext;
    if (g_isU8) {
        const unsigned char* p = (const unsigned char*)mask + (size_t)b * SS;
        on = p[s] != 0;
        onNext = (s + 1 < SS) ? (p[s + 1] != 0) : false;
    } else {
        const unsigned int* p = (const unsigned int*)mask + (size_t)b * SS;
        on = p[s] != 0;
        onNext = (s + 1 < SS) ? (p[s + 1] != 0) : false;
    }

    double term = 0.0;
    if (on) {
        const int* tg = tags + (size_t)b * SS;
        int tag  = tg[s];
        int prev = (s == 0) ? START_TAG : tg[s - 1];
        term = (double)feats[((size_t)b * SS + s) * TT + tag]
             + (double)tr[prev * TT + tag];
        if (!onNext)                         // last valid position
            term += (double)tr[tag * TT + END_TAG];
    }
    unsigned bal = __ballot_sync(0xffffffffu, on);
    #pragma unroll
    for (int o = 16; o; o >>= 1) term += __shfl_xor_sync(0xffffffffu, term, o);
    if ((tid & 31) == 0) { sg[tid >> 5] = term; sc[tid >> 5] = __popc(bal); }
    __syncthreads();
    if (tid == 0) {
        double acc = 0.0; int cnt = 0;
        #pragma unroll
        for (int i = 0; i < 8; i++) { acc += sg[i]; cnt += sc[i]; }
        g_goldp[b][c] = acc;
        g_lenp[b][c] = cnt;
    }
}

// ---------------- forward/backward scan, single-warp CTAs ----------------
// CTA 0..511: forward alpha over s=0..m; CTA 512..1023: backward beta over
// s=len-1..m, m=(len-1)/2. Thread t<26 owns tag pair (2t, 2t+1); the 13
// LDS.128 q-loads are shared by both matvecs. Length = one broadcast int4
// load of chunk partials (no front-batched mask scan — that caused the
// round-8 L1tex-queue spread regression).
__global__ void __launch_bounds__(32, 1) k_main(const float* __restrict__ feats,
                                                const float* __restrict__ tr) {
    const int cta = blockIdx.x;
    const int b = cta & (BB - 1);
    const bool isFwd = cta < BB;
    const int t = threadIdx.x;            // 0..31
    const bool act = (t < 26);
    const int tcl = act ? t : 25;
    const int jA = act ? 2 * t : 50;
    const int jB = act ? 2 * t + 1 : 51;
    __shared__ __align__(16) float shq[2][64];

    const int4 lp = *(const int4*)g_lenp[b];   // broadcast, 1 LDG
    const int len = lp.x + lp.y + lp.z + lp.w;

    const int m = (len - 1) >> 1;
    const float* fb = feats + (size_t)b * SS * TT;
    const ull L2E2 = f2pack(LOG2E, LOG2E);

    if (isFwd) {
        const int L = m + 1;              // steps s=1..m
        // E columns jA, jB packed over i-pairs
        ull EpA[26], EpB[26];
        #pragma unroll
        for (int c = 0; c < 26; c++) {
            EpA[c] = f2pack(g_E[(2 * c) * TT + jA], g_E[(2 * c + 1) * TT + jA]);
            EpB[c] = f2pack(g_E[(2 * c) * TT + jB], g_E[(2 * c + 1) * TT + jB]);
        }

        // init: part0 = feats[b,0,:] + trans[START,:]
        float p0A = act ? (fb[jA] + tr[START_TAG * TT + jA]) : -1e30f;
        float p0B = act ? (fb[jB] + tr[START_TAG * TT + jB]) : -1e30f;
        float mx = fmaxf(p0A, p0B);
        #pragma unroll
        for (int o = 16; o; o >>= 1)
            mx = fmaxf(mx, __shfl_xor_sync(0xffffffffu, mx, o));
        const float m0 = mx;
        float uA = act ? ex2((p0A - m0) * LOG2E) : 0.0f;
        float uB = act ? ex2((p0B - m0) * LOG2E) : 0.0f;
        ((float2*)shq[0])[t] = make_float2(uA, uB);
        int Ktot = 0;
        __syncwarp();

        // emission pair prefetch (distance 4), pre-scaled by log2e
        const float2* pe = (const float2*)fb + tcl;   // stride 26 float2/step
        ull fl0 = 0, fl1 = 0, fl2 = 0, fl3 = 0;
        if (1 < L) { float2 v = pe[1 * 26]; fl0 = f2mul(f2pack(v.x, v.y), L2E2); }
        if (2 < L) { float2 v = pe[2 * 26]; fl1 = f2mul(f2pack(v.x, v.y), L2E2); }
        if (3 < L) { float2 v = pe[3 * 26]; fl2 = f2mul(f2pack(v.x, v.y), L2E2); }
        if (4 < L) { float2 v = pe[4 * 26]; fl3 = f2mul(f2pack(v.x, v.y), L2E2); }

        for (int s = 1; s < L; s++) {
            float2 fc = f2unpack(fl0);
            float efA = ex2(fc.x), efB = ex2(fc.y);
            fl0 = fl1; fl1 = fl2; fl2 = fl3;
            int sp = s + 4;
            float2 nv = make_float2(0.f, 0.f);
            if (sp < L) nv = pe[sp * 26];
            fl3 = f2mul(f2pack(nv.x, nv.y), L2E2);

            const ulonglong2* q8 = (const ulonglong2*)shq[(s - 1) & 1];
            ulonglong2 qv[13];
            #pragma unroll
            for (int c = 0; c < 13; c++) qv[c] = q8[c];

            float q0 = f2lo(qv[0].x);
            int ex = ((__float_as_int(q0) >> 23) & 0xFF) - 127;
            Ktot += ex;
            float scale = __int_as_float((127 - ex) << 23);
            float preA = scale * efA, preB = scale * efB;

            uA = matvec26(qv, EpA) * preA;
            uB = matvec26(qv, EpB) * preB;

            float2 st = act ? make_float2(uA, uB) : make_float2(0.f, 0.f);
            ((float2*)shq[s & 1])[t] = st;
            __syncwarp();
        }
        if (act) ((float2*)g_alpha[b])[t] = make_float2(uA, uB);
        if (t == 0) { g_Ka[b] = Ktot; g_m0[b] = m0; }
    } else {
        const int N = len - 1 - m;        // iterations: s = len-2 .. m
        // E rows jA, jB packed over column-pairs (contiguous 8B loads)
        ull EpA[26], EpB[26];
        const ull* ErA = (const ull*)(g_E + jA * TT);
        const ull* ErB = (const ull*)(g_E + jB * TT);
        #pragma unroll
        for (int c = 0; c < 26; c++) { EpA[c] = ErA[c]; EpB[c] = ErB[c]; }

        float EendA = g_E[jA * TT + END_TAG];
        float EendB = g_E[jB * TT + END_TAG];
        float uA, uB;
        if (len >= 2) {
            const float* fl = fb + (size_t)(len - 1) * TT;
            uA = ex2(fl[jA] * LOG2E) * EendA;
            uB = ex2(fl[jB] * LOG2E) * EendB;
        } else {
            uA = EendA; uB = EendB;       // len==1: beta = E[:,END], no ef
        }
        if (!act) { uA = 0.f; uB = 0.f; }
        ((float2*)shq[0])[t] = make_float2(uA, uB);
        int Ktot = 0;
        __syncwarp();

        // emission f_s needed only for iterations k <= N-2 (ef==1 at s==m)
        const float2* pb = (const float2*)fb + tcl;
        ull fl0 = 0, fl1 = 0, fl2 = 0, fl3 = 0;
        if (N >= 2) { float2 v = pb[(size_t)(len - 2) * 26]; fl0 = f2mul(f2pack(v.x, v.y), L2E2); }
        if (N >= 3) { float2 v = pb[(size_t)(len - 3) * 26]; fl1 = f2mul(f2pack(v.x, v.y), L2E2); }
        if (N >= 4) { float2 v = pb[(size_t)(len - 4) * 26]; fl2 = f2mul(f2pack(v.x, v.y), L2E2); }
        if (N >= 5) { float2 v = pb[(size_t)(len - 5) * 26]; fl3 = f2mul(f2pack(v.x, v.y), L2E2); }

        for (int k = 0; k < N; k++) {
            float2 fc = f2unpack(fl0);
            float efA = ex2(fc.x), efB = ex2(fc.y);
            fl0 = fl1; fl1 = fl2; fl2 = fl3;
            int kk = k + 4;
            float2 nv = make_float2(0.f, 0.f);
            if (kk <= N - 2) nv = pb[(size_t)(len - 2 - kk) * 26];
            fl3 = f2mul(f2pack(nv.x, nv.y), L2E2);

            const ulonglong2* q8 = (const ulonglong2*)shq[k & 1];
            ulonglong2 qv[13];
            #pragma unroll
            for (int c = 0; c < 13; c++) qv[c] = q8[c];

            float q0 = f2lo(qv[0].x);
            int ex = ((__float_as_int(q0) >> 23) & 0xFF) - 127;
            Ktot += ex;
            float scale = __int_as_float((127 - ex) << 23);
            float preA = scale * efA, preB = scale * efB;

            uA = matvec26(qv, EpA) * preA;
            uB = matvec26(qv, EpB) * preB;

            float2 st = act ? make_float2(uA, uB) : make_float2(0.f, 0.f);
            ((float2*)shq[(k + 1) & 1])[t] = st;
            __syncwarp();
        }
        if (act) ((float2*)g_beta[b])[t] = make_float2(uA, uB);
        if (t == 0) g_Kb[b] = Ktot;
    }
}

// ---------------- combine: logZ_b - gold_b ----------------
__global__ void k_combine() {
    int b = blockIdx.x;
    int l = threadIdx.x;   // 32
    double d = (double)g_alpha[b][l] * (double)g_beta[b][l];
    if (l < TT - 32)
        d += (double)g_alpha[b][l + 32] * (double)g_beta[b][l + 32];
    #pragma unroll
    for (int o = 16; o; o >>= 1) d += __shfl_xor_sync(0xffffffffu, d, o);
    if (l == 0) {
        double gold = g_goldp[b][0] + g_goldp[b][1]
                    + g_goldp[b][2] + g_goldp[b][3];
        double logZ = (double)g_m0[b] +
                      (double)(g_Ka[b] + g_Kb[b]) * LN2 + log(d);
        g_final[b] = logZ - gold;
    }
}

// ---------------- final reduction ----------------
__global__ void k_reduce(float* out) {
    __shared__ double sh[16];
    int tid = threadIdx.x;  // 512 threads
    double a = g_final[tid];
    #pragma unroll
    for (int o = 16; o; o >>= 1) a += __shfl_xor_sync(0xffffffffu, a, o);
    if ((tid & 31) == 0) sh[tid >> 5] = a;
    __syncthreads();
    if (tid < 32) {
        double v = (tid < 16) ? sh[tid] : 0.0;
        #pragma unroll
        for (int o = 8; o; o >>= 1) v += __shfl_xor_sync(0xffffffffu, v, o);
        if (tid == 0) out[0] = (float)v;
    }
}

// ---------------- launch ----------------
extern "C" void kernel_launch(void* const* d_in, const int* in_sizes, int n_in,
                              void* d_out, int out_size) {
    const float* feats = (const float*)d_in[0];
    const void*  mask  = d_in[1];
    const int*   tags  = (const int*)d_in[2];
    const float* tr    = (const float*)d_in[3];
    float* out = (float*)d_out;

    k_detect<<<1, 256>>>(mask, tr);
    k_gold2<<<4 * BB, 256>>>(mask, feats, tags, tr);
    k_main<<<2 * BB, 32>>>(feats, tr);
    k_combine<<<BB, 32>>>();
    k_reduce<<<1, 512>>>(out);
}

// round 10
// speedup vs baseline: 1.7935x; 1.1513x over previous
#include <cuda_runtime.h>
#include <math.h>

#define BB 512
#define SS 1024
#define TT 52
#define START_TAG 50
#define END_TAG 51
#define LOG2E 1.4426950408889634f
#define LN2 0.6931471805599453

typedef unsigned long long ull;

// ---------------- device scratch (no allocations allowed) ----------------
__device__ __align__(16) float g_E[TT * TT];    // exp(transitions)
__device__ __align__(16) float g_ET[TT * TT];   // transposed copy
__device__ int    g_isU8;
__device__ __align__(16) int g_lenp[BB][4];     // per-chunk length partials
__device__ __align__(8) float g_alpha[BB][64];  // zero-init; only [0..49] written
__device__ __align__(8) float g_beta[BB][64];
__device__ int    g_Ka[BB], g_Kb[BB];
__device__ float  g_m0[BB];
__device__ double g_goldp[BB][4];
__device__ double g_final[BB];

// ---------------- packed f32x2 helpers (Blackwell) ----------------
__device__ __forceinline__ ull f2pack(float lo, float hi) {
    ull r;
    asm("mov.b64 %0, {%1, %2};" : "=l"(r) : "f"(lo), "f"(hi));
    return r;
}
__device__ __forceinline__ float2 f2unpack(ull a) {
    float2 r;
    asm("mov.b64 {%0, %1}, %2;" : "=f"(r.x), "=f"(r.y) : "l"(a));
    return r;
}
__device__ __forceinline__ float f2lo(ull a) {
    float r;
    asm("{ .reg .b32 hi; mov.b64 {%0, hi}, %1; }" : "=f"(r) : "l"(a));
    return r;
}
__device__ __forceinline__ ull f2fma(ull a, ull b, ull c) {
    ull d;
    asm("fma.rn.f32x2 %0, %1, %2, %3;" : "=l"(d) : "l"(a), "l"(b), "l"(c));
    return d;
}
__device__ __forceinline__ ull f2mul(ull a, ull b) {
    ull d;
    asm("mul.rn.f32x2 %0, %1, %2;" : "=l"(d) : "l"(a), "l"(b));
    return d;
}
__device__ __forceinline__ ull f2add(ull a, ull b) {
    ull d;
    asm("add.rn.f32x2 %0, %1, %2;" : "=l"(d) : "l"(a), "l"(b));
    return d;
}
__device__ __forceinline__ float ex2(float x) {
    float y;
    asm("ex2.approx.ftz.f32 %0, %1;" : "=f"(y) : "f"(x));
    return y;
}

// matvec over i=0..49 (25 packed pairs), 4 accumulators
__device__ __forceinline__ float matvec25(const ulonglong2* qv, const ull* Ep) {
    ull a0 = f2mul(qv[0].x, Ep[0]);
    ull a1 = f2mul(qv[0].y, Ep[1]);
    ull a2 = f2mul(qv[1].x, Ep[2]);
    ull a3 = f2mul(qv[1].y, Ep[3]);
    #pragma unroll
    for (int c = 2; c < 12; c++) {
        if (c & 1) {
            a2 = f2fma(qv[c].x, Ep[2 * c],     a2);
            a3 = f2fma(qv[c].y, Ep[2 * c + 1], a3);
        } else {
            a0 = f2fma(qv[c].x, Ep[2 * c],     a0);
            a1 = f2fma(qv[c].y, Ep[2 * c + 1], a1);
        }
    }
    a0 = f2fma(qv[12].x, Ep[24], a0);   // pair (48,49)
    a2 = f2add(a2, a3);
    a0 = f2add(a0, a1);
    a0 = f2add(a0, a2);
    float2 h = f2unpack(a0);
    return h.x + h.y;
}

// ---------------- mask dtype detection + E / E^T tables ----------------
__global__ void k_detect(const void* mask, const float* __restrict__ tr) {
    int tid = threadIdx.x;     // 256
    if (tid < 32) {
        const unsigned char* p = (const unsigned char*)mask;
        int any = 0;
        for (int b = tid; b < BB; b += 32)
            any |= (int)p[(size_t)b * SS + 1];
        #pragma unroll
        for (int o = 16; o; o >>= 1) any |= __shfl_xor_sync(0xffffffffu, any, o);
        if (tid == 0) g_isU8 = (any != 0);
    }
    for (int idx = tid; idx < TT * TT; idx += 256) {
        float e = expf(tr[idx]);
        g_E[idx] = e;
        g_ET[(idx % TT) * TT + (idx / TT)] = e;
    }
}

// ---------------- length partials: one thread per (b, s) -----------------
__global__ void k_len(const void* mask) {
    int b   = blockIdx.x >> 2;
    int c   = blockIdx.x & 3;
    int tid = threadIdx.x;       // 256
    int s   = (c << 8) + tid;
    __shared__ int sc[8];
    bool on;
    if (g_isU8) on = ((const unsigned char*)mask)[(size_t)b * SS + s] != 0;
    else        on = ((const unsigned int*)mask)[(size_t)b * SS + s] != 0;
    unsigned bal = __ballot_sync(0xffffffffu, on);
    if ((tid & 31) == 0) sc[tid >> 5] = __popc(bal);
    __syncthreads();
    if (tid == 0) {
        int cnt = 0;
        #pragma unroll
        for (int i = 0; i < 8; i++) cnt += sc[i];
        g_lenp[b][c] = cnt;
    }
}

// ---------------- gold partials: one thread per (b, s) -------------------
__global__ void k_gold2(const void* mask,
                        const float* __restrict__ feats,
                        const int* __restrict__ tags,
                        const float* __restrict__ tr) {
    int b   = blockIdx.x >> 2;
    int c   = blockIdx.x & 3;
    int tid = threadIdx.x;       // 256
    int s   = (c << 8) + tid;
    __shared__ double sg[8];

    bool on, onNext;
    if (g_isU8) {
        const unsigned char* p = (const unsigned char*)mask + (size_t)b * SS;
        on = p[s] != 0;
        onNext = (s + 1 < SS) ? (p[s + 1] != 0) : false;
    } else {
        const unsigned int* p = (const unsigned int*)mask + (size_t)b * SS;
        on = p[s] != 0;
        onNext = (s + 1 < SS) ? (p[s + 1] != 0) : false;
    }

    double term = 0.0;
    if (on) {
        const int* tg = tags + (size_t)b * SS;
        int tag  = tg[s];
        int prev = (s == 0) ? START_TAG : tg[s - 1];
        term = (double)feats[((size_t)b * SS + s) * TT + tag]
             + (double)tr[prev * TT + tag];
        if (!onNext)                         // last valid position
            term += (double)tr[tag * TT + END_TAG];
    }
    #pragma unroll
    for (int o = 16; o; o >>= 1) term += __shfl_xor_sync(0xffffffffu, term, o);
    if ((tid & 31) == 0) sg[tid >> 5] = term;
    __syncthreads();
    if (tid == 0) {
        double acc = 0.0;
        #pragma unroll
        for (int i = 0; i < 8; i++) acc += sg[i];
        g_goldp[b][c] = acc;
    }
}

// ---------------- forward/backward scan, single-warp CTAs ----------------
// CTA 0..511: forward alpha over s=0..m; CTA 512..1023: backward beta over
// s=len-1..m, m=(len-1)/2. 50 effective tags (START column / END row of E
// are exactly 0 in fp32): thread t<25 owns tag pair (2t, 2t+1); matvec is
// 25 f2fma per column. Step loop unrolled x2 with static buffer indices.
__global__ void __launch_bounds__(32, 1) k_main(const float* __restrict__ feats,
                                                const float* __restrict__ tr) {
    const int cta = blockIdx.x;
    const int b = cta & (BB - 1);
    const bool isFwd = cta < BB;
    const int t = threadIdx.x;            // 0..31
    const bool act = (t < 25);
    const int tcl = act ? t : 24;
    const int jA = act ? 2 * t : 48;
    const int jB = act ? 2 * t + 1 : 49;
    __shared__ __align__(16) float shq[2][64];

    const int4 lp = *(const int4*)g_lenp[b];   // broadcast, 1 LDG
    const int len = lp.x + lp.y + lp.z + lp.w;

    const int m = (len - 1) >> 1;
    const float* fb = feats + (size_t)b * SS * TT;
    const ull L2E2 = f2pack(LOG2E, LOG2E);
    float uA, uB;
    int Ktot = 0;

    if (isFwd) {
        const int L = m + 1;              // steps s=1..m
        // E columns jA, jB via transposed table: coalesced ull loads
        ull EpA[25], EpB[25];
        const ull* EcA = (const ull*)(g_ET + jA * TT);
        const ull* EcB = (const ull*)(g_ET + jB * TT);
        #pragma unroll
        for (int c = 0; c < 25; c++) { EpA[c] = EcA[c]; EpB[c] = EcB[c]; }

        // init: part0 = feats[b,0,:] + trans[START,:]
        float p0A = act ? (fb[jA] + tr[START_TAG * TT + jA]) : -1e30f;
        float p0B = act ? (fb[jB] + tr[START_TAG * TT + jB]) : -1e30f;
        float mx = fmaxf(p0A, p0B);
        #pragma unroll
        for (int o = 16; o; o >>= 1)
            mx = fmaxf(mx, __shfl_xor_sync(0xffffffffu, mx, o));
        const float m0 = mx;
        uA = act ? ex2((p0A - m0) * LOG2E) : 0.0f;
        uB = act ? ex2((p0B - m0) * LOG2E) : 0.0f;
        ((float2*)shq[0])[t] = make_float2(uA, uB);
        __syncwarp();

        // emission pair prefetch (distance 4), pre-scaled by log2e
        const float2* pe = (const float2*)fb + tcl;   // stride 26 float2/step
        ull fl0 = 0, fl1 = 0, fl2 = 0, fl3 = 0;
        if (1 < L) { float2 v = pe[1 * 26]; fl0 = f2mul(f2pack(v.x, v.y), L2E2); }
        if (2 < L) { float2 v = pe[2 * 26]; fl1 = f2mul(f2pack(v.x, v.y), L2E2); }
        if (3 < L) { float2 v = pe[3 * 26]; fl2 = f2mul(f2pack(v.x, v.y), L2E2); }
        if (4 < L) { float2 v = pe[4 * 26]; fl3 = f2mul(f2pack(v.x, v.y), L2E2); }

#define FSTEP(SRC, DST) {                                                     \
        float2 fc = f2unpack(fl0);                                            \
        float efA = ex2(fc.x), efB = ex2(fc.y);                               \
        fl0 = fl1; fl1 = fl2; fl2 = fl3;                                      \
        int sp = s + 4;                                                       \
        float2 nv = make_float2(0.f, 0.f);                                    \
        if (sp < L) nv = pe[sp * 26];                                         \
        fl3 = f2mul(f2pack(nv.x, nv.y), L2E2);                                \
        const ulonglong2* q8 = (const ulonglong2*)shq[SRC];                   \
        ulonglong2 qv[13];                                                    \
        _Pragma("unroll") for (int c = 0; c < 13; c++) qv[c] = q8[c];         \
        float q0 = f2lo(qv[0].x);                                             \
        int exq = ((__float_as_int(q0) >> 23) & 0xFF) - 127;                  \
        Ktot += exq;                                                          \
        float scale = __int_as_float((127 - exq) << 23);                      \
        uA = matvec25(qv, EpA) * (scale * efA);                               \
        uB = matvec25(qv, EpB) * (scale * efB);                               \
        float2 st = act ? make_float2(uA, uB) : make_float2(0.f, 0.f);        \
        ((float2*)shq[DST])[t] = st;                                          \
        __syncwarp();                                                         \
        s++;                                                                  \
    }
        int s = 1;
        while (s + 1 < L) { FSTEP(0, 1) FSTEP(1, 0) }
        if (s < L) { FSTEP(0, 1) }
#undef FSTEP
        if (act) ((float2*)g_alpha[b])[t] = make_float2(uA, uB);
        if (t == 0) { g_Ka[b] = Ktot; g_m0[b] = m0; }
    } else {
        const int N = len - 1 - m;        // iterations: s = len-2 .. m
        // E rows jA, jB (contiguous 8B loads), k=0..49
        ull EpA[25], EpB[25];
        const ull* ErA = (const ull*)(g_E + jA * TT);
        const ull* ErB = (const ull*)(g_E + jB * TT);
        #pragma unroll
        for (int c = 0; c < 25; c++) { EpA[c] = ErA[c]; EpB[c] = ErB[c]; }

        float EendA = g_E[jA * TT + END_TAG];
        float EendB = g_E[jB * TT + END_TAG];
        if (len >= 2) {
            const float* fl = fb + (size_t)(len - 1) * TT;
            uA = ex2(fl[jA] * LOG2E) * EendA;
            uB = ex2(fl[jB] * LOG2E) * EendB;
        } else {
            uA = EendA; uB = EendB;       // len==1: beta = E[:,END], no ef
        }
        if (!act) { uA = 0.f; uB = 0.f; }
        ((float2*)shq[0])[t] = make_float2(uA, uB);
        __syncwarp();

        // emission f_s needed only for iterations k <= N-2 (ef==1 at s==m)
        const float2* pb = (const float2*)fb + tcl;
        ull fl0 = 0, fl1 = 0, fl2 = 0, fl3 = 0;
        if (N >= 2) { float2 v = pb[(size_t)(len - 2) * 26]; fl0 = f2mul(f2pack(v.x, v.y), L2E2); }
        if (N >= 3) { float2 v = pb[(size_t)(len - 3) * 26]; fl1 = f2mul(f2pack(v.x, v.y), L2E2); }
        if (N >= 4) { float2 v = pb[(size_t)(len - 4) * 26]; fl2 = f2mul(f2pack(v.x, v.y), L2E2); }
        if (N >= 5) { float2 v = pb[(size_t)(len - 5) * 26]; fl3 = f2mul(f2pack(v.x, v.y), L2E2); }

#define BSTEP(SRC, DST) {                                                     \
        float2 fc = f2unpack(fl0);                                            \
        float efA = ex2(fc.x), efB = ex2(fc.y);                               \
        fl0 = fl1; fl1 = fl2; fl2 = fl3;                                      \
        int kk = k + 4;                                                       \
        float2 nv = make_float2(0.f, 0.f);                                    \
        if (kk <= N - 2) nv = pb[(size_t)(len - 2 - kk) * 26];                \
        fl3 = f2mul(f2pack(nv.x, nv.y), L2E2);                                \
        const ulonglong2* q8 = (const ulonglong2*)shq[SRC];                   \
        ulonglong2 qv[13];                                                    \
        _Pragma("unroll") for (int c = 0; c < 13; c++) qv[c] = q8[c];         \
        float q0 = f2lo(qv[0].x);                                             \
        int exq = ((__float_as_int(q0) >> 23) & 0xFF) - 127;                  \
        Ktot += exq;                                                          \
        float scale = __int_as_float((127 - exq) << 23);                      \
        uA = matvec25(qv, EpA) * (scale * efA);                               \
        uB = matvec25(qv, EpB) * (scale * efB);                               \
        float2 st = act ? make_float2(uA, uB) : make_float2(0.f, 0.f);        \
        ((float2*)shq[DST])[t] = st;                                          \
        __syncwarp();                                                         \
        k++;                                                                  \
    }
        int k = 0;
        while (k + 1 < N) { BSTEP(0, 1) BSTEP(1, 0) }
        if (k < N) { BSTEP(0, 1) }
#undef BSTEP
        if (act) ((float2*)g_beta[b])[t] = make_float2(uA, uB);
        if (t == 0) g_Kb[b] = Ktot;
    }
}

// ---------------- combine: logZ_b - gold_b ----------------
__global__ void k_combine() {
    int b = blockIdx.x;
    int l = threadIdx.x;   // 32
    double d = (double)g_alpha[b][l] * (double)g_beta[b][l];
    if (l < 18)
        d += (double)g_alpha[b][l + 32] * (double)g_beta[b][l + 32];
    #pragma unroll
    for (int o = 16; o; o >>= 1) d += __shfl_xor_sync(0xffffffffu, d, o);
    if (l == 0) {
        double gold = g_goldp[b][0] + g_goldp[b][1]
                    + g_goldp[b][2] + g_goldp[b][3];
        double logZ = (double)g_m0[b] +
                      (double)(g_Ka[b] + g_Kb[b]) * LN2 + log(d);
        g_final[b] = logZ - gold;
    }
}

// ---------------- final reduction ----------------
__global__ void k_reduce(float* out) {
    __shared__ double sh[16];
    int tid = threadIdx.x;  // 512 threads
    double a = g_final[tid];
    #pragma unroll
    for (int o = 16; o; o >>= 1) a += __shfl_xor_sync(0xffffffffu, a, o);
    if ((tid & 31) == 0) sh[tid >> 5] = a;
    __syncthreads();
    if (tid < 32) {
        double v = (tid < 16) ? sh[tid] : 0.0;
        #pragma unroll
        for (int o = 8; o; o >>= 1) v += __shfl_xor_sync(0xffffffffu, v, o);
        if (tid == 0) out[0] = (float)v;
    }
}

// ---------------- launch (fork-join: gold2 overlaps k_main) ----------------
extern "C" void kernel_launch(void* const* d_in, const int* in_sizes, int n_in,
                              void* d_out, int out_size) {
    const float* feats = (const float*)d_in[0];
    const void*  mask  = d_in[1];
    const int*   tags  = (const int*)d_in[2];
    const float* tr    = (const float*)d_in[3];
    float* out = (float*)d_out;

    cudaStream_t s2 = 0;
    cudaEvent_t evA = 0, evB = 0;
    bool forked =
        (cudaStreamCreateWithFlags(&s2, cudaStreamNonBlocking) == cudaSuccess) &&
        (cudaEventCreateWithFlags(&evA, cudaEventDisableTiming) == cudaSuccess) &&
        (cudaEventCreateWithFlags(&evB, cudaEventDisableTiming) == cudaSuccess);

    k_detect<<<1, 256>>>(mask, tr);
    k_len<<<4 * BB, 256>>>(mask);

    if (forked) {
        cudaEventRecord(evA, 0);
        cudaStreamWaitEvent(s2, evA, 0);
        k_gold2<<<4 * BB, 256, 0, s2>>>(mask, feats, tags, tr);
        k_main<<<2 * BB, 32>>>(feats, tr);
        cudaEventRecord(evB, s2);
        cudaStreamWaitEvent(0, evB, 0);
    } else {
        k_gold2<<<4 * BB, 256>>>(mask, feats, tags, tr);
        k_main<<<2 * BB, 32>>>(feats, tr);
    }

    k_combine<<<BB, 32>>>();
    k_reduce<<<1, 512>>>(out);

    if (forked) {
        cudaEventDestroy(evA);
        cudaEventDestroy(evB);
        cudaStreamDestroy(s2);
    }
}

// round 11
// speedup vs baseline: 2.1062x; 1.1743x over previous
#include <cuda_runtime.h>
#include <math.h>

#define BB 512
#define SS 1024
#define TT 52
#define START_TAG 50
#define END_TAG 51
#define LOG2E 1.4426950408889634f
#define LN2 0.6931471805599453

typedef unsigned long long ull;

// ---------------- device scratch (no allocations allowed) ----------------
__device__ __align__(16) float g_E[TT * TT];    // exp(transitions)
__device__ __align__(16) float g_ET[TT * TT];   // transposed copy
__device__ int    g_isU8;
__device__ __align__(16) int g_lenp[BB][4];     // per-chunk length partials
__device__ int    g_task[BB];                   // sequence ids, length-descending
__device__ __align__(8) float g_alpha[BB][64];
__device__ __align__(8) float g_beta[BB][64];
__device__ int    g_Ka[BB], g_Kb[BB];
__device__ float  g_m0[BB];
__device__ double g_goldp[BB][4];
__device__ double g_final[BB];

// ---------------- packed f32x2 helpers (Blackwell) ----------------
__device__ __forceinline__ ull f2pack(float lo, float hi) {
    ull r;
    asm("mov.b64 %0, {%1, %2};" : "=l"(r) : "f"(lo), "f"(hi));
    return r;
}
__device__ __forceinline__ float2 f2unpack(ull a) {
    float2 r;
    asm("mov.b64 {%0, %1}, %2;" : "=f"(r.x), "=f"(r.y) : "l"(a));
    return r;
}
__device__ __forceinline__ float f2lo(ull a) {
    float r;
    asm("{ .reg .b32 hi; mov.b64 {%0, hi}, %1; }" : "=f"(r) : "l"(a));
    return r;
}
__device__ __forceinline__ ull f2fma(ull a, ull b, ull c) {
    ull d;
    asm("fma.rn.f32x2 %0, %1, %2, %3;" : "=l"(d) : "l"(a), "l"(b), "l"(c));
    return d;
}
__device__ __forceinline__ ull f2mul(ull a, ull b) {
    ull d;
    asm("mul.rn.f32x2 %0, %1, %2;" : "=l"(d) : "l"(a), "l"(b));
    return d;
}
__device__ __forceinline__ ull f2add(ull a, ull b) {
    ull d;
    asm("add.rn.f32x2 %0, %1, %2;" : "=l"(d) : "l"(a), "l"(b));
    return d;
}
__device__ __forceinline__ float ex2(float x) {
    float y;
    asm("ex2.approx.ftz.f32 %0, %1;" : "=f"(y) : "f"(x));
    return y;
}

// matvec over i=0..49 (25 packed pairs), 4 accumulators
__device__ __forceinline__ float matvec25(const ulonglong2* qv, const ull* Ep) {
    ull a0 = f2mul(qv[0].x, Ep[0]);
    ull a1 = f2mul(qv[0].y, Ep[1]);
    ull a2 = f2mul(qv[1].x, Ep[2]);
    ull a3 = f2mul(qv[1].y, Ep[3]);
    #pragma unroll
    for (int c = 2; c < 12; c++) {
        if (c & 1) {
            a2 = f2fma(qv[c].x, Ep[2 * c],     a2);
            a3 = f2fma(qv[c].y, Ep[2 * c + 1], a3);
        } else {
            a0 = f2fma(qv[c].x, Ep[2 * c],     a0);
            a1 = f2fma(qv[c].y, Ep[2 * c + 1], a1);
        }
    }
    a0 = f2fma(qv[12].x, Ep[24], a0);   // pair (48,49)
    a2 = f2add(a2, a3);
    a0 = f2add(a0, a1);
    a0 = f2add(a0, a2);
    float2 h = f2unpack(a0);
    return h.x + h.y;
}

// ---------------- mask dtype detection + E / E^T tables ----------------
__global__ void k_detect(const void* mask, const float* __restrict__ tr) {
    int tid = threadIdx.x;     // 256
    if (tid < 32) {
        const unsigned char* p = (const unsigned char*)mask;
        int any = 0;
        for (int b = tid; b < BB; b += 32)
            any |= (int)p[(size_t)b * SS + 1];
        #pragma unroll
        for (int o = 16; o; o >>= 1) any |= __shfl_xor_sync(0xffffffffu, any, o);
        if (tid == 0) g_isU8 = (any != 0);
    }
    for (int idx = tid; idx < TT * TT; idx += 256) {
        float e = expf(tr[idx]);
        g_E[idx] = e;
        g_ET[(idx % TT) * TT + (idx / TT)] = e;
    }
}

// ---------------- length partials: one thread per (b, s) -----------------
__global__ void k_len(const void* mask) {
    int b   = blockIdx.x >> 2;
    int c   = blockIdx.x & 3;
    int tid = threadIdx.x;       // 256
    int s   = (c << 8) + tid;
    __shared__ int sc[8];
    bool on;
    if (g_isU8) on = ((const unsigned char*)mask)[(size_t)b * SS + s] != 0;
    else        on = ((const unsigned int*)mask)[(size_t)b * SS + s] != 0;
    unsigned bal = __ballot_sync(0xffffffffu, on);
    if ((tid & 31) == 0) sc[tid >> 5] = __popc(bal);
    __syncthreads();
    if (tid == 0) {
        int cnt = 0;
        #pragma unroll
        for (int i = 0; i < 8; i++) cnt += sc[i];
        g_lenp[b][c] = cnt;
    }
}

// ---------------- rank sequences by length (descending) — LPT order ------
// One CTA, 512 threads. rank_b = #(len_c > len_b) + ties broken by index.
// Longest-first dealing across SMs balances per-SM aggregate load.
__global__ void k_rank() {
    __shared__ int sl[BB];
    int b = threadIdx.x;         // 512
    int4 lp = *(const int4*)g_lenp[b];
    int len = lp.x + lp.y + lp.z + lp.w;
    sl[b] = len;
    __syncthreads();
    int r = 0;
    #pragma unroll 8
    for (int c = 0; c < BB; c++) {
        int lc = sl[c];
        r += (lc > len) || (lc == len && c < b);
    }
    g_task[r] = b;
}

// ---------------- gold partials: one thread per (b, s) -------------------
__global__ void k_gold2(const void* mask,
                        const float* __restrict__ feats,
                        const int* __restrict__ tags,
                        const float* __restrict__ tr) {
    int b   = blockIdx.x >> 2;
    int c   = blockIdx.x & 3;
    int tid = threadIdx.x;       // 256
    int s   = (c << 8) + tid;
    __shared__ double sg[8];

    bool on, onNext;
    if (g_isU8) {
        const unsigned char* p = (const unsigned char*)mask + (size_t)b * SS;
        on = p[s] != 0;
        onNext = (s + 1 < SS) ? (p[s + 1] != 0) : false;
    } else {
        const unsigned int* p = (const unsigned int*)mask + (size_t)b * SS;
        on = p[s] != 0;
        onNext = (s + 1 < SS) ? (p[s + 1] != 0) : false;
    }

    double term = 0.0;
    if (on) {
        const int* tg = tags + (size_t)b * SS;
        int tag  = tg[s];
        int prev = (s == 0) ? START_TAG : tg[s - 1];
        term = (double)feats[((size_t)b * SS + s) * TT + tag]
             + (double)tr[prev * TT + tag];
        if (!onNext)                         // last valid position
            term += (double)tr[tag * TT + END_TAG];
    }
    #pragma unroll
    for (int o = 16; o; o >>= 1) term += __shfl_xor_sync(0xffffffffu, term, o);
    if ((tid & 31) == 0) sg[tid >> 5] = term;
    __syncthreads();
    if (tid == 0) {
        double acc = 0.0;
        #pragma unroll
        for (int i = 0; i < 8; i++) acc += sg[i];
        g_goldp[b][c] = acc;
    }
}

// ---------------- forward/backward scan, single-warp CTAs ----------------
// Task (cta>>1) = rank in length-descending order -> b = g_task[rank];
// dir = cta&1 (0 fwd, 1 bwd). Longest tasks get the lowest bids, so static
// placement stripes them evenly across SMs (LPT balance).
__global__ void __launch_bounds__(32, 1) k_main(const float* __restrict__ feats,
                                                const float* __restrict__ tr) {
    const int cta = blockIdx.x;
    const int b = g_task[cta >> 1];
    const bool isFwd = (cta & 1) == 0;
    const int t = threadIdx.x;            // 0..31
    const bool act = (t < 25);
    const int tcl = act ? t : 24;
    const int jA = act ? 2 * t : 48;
    const int jB = act ? 2 * t + 1 : 49;
    __shared__ __align__(16) float shq[2][64];

    const int4 lp = *(const int4*)g_lenp[b];   // broadcast, 1 LDG
    const int len = lp.x + lp.y + lp.z + lp.w;

    const int m = (len - 1) >> 1;
    const float* fb = feats + (size_t)b * SS * TT;
    const ull L2E2 = f2pack(LOG2E, LOG2E);
    float uA, uB;
    int Ktot = 0;

    if (isFwd) {
        const int L = m + 1;              // steps s=1..m
        // E columns jA, jB via transposed table: coalesced ull loads
        ull EpA[25], EpB[25];
        const ull* EcA = (const ull*)(g_ET + jA * TT);
        const ull* EcB = (const ull*)(g_ET + jB * TT);
        #pragma unroll
        for (int c = 0; c < 25; c++) { EpA[c] = EcA[c]; EpB[c] = EcB[c]; }

        // init: part0 = feats[b,0,:] + trans[START,:]
        float p0A = act ? (fb[jA] + tr[START_TAG * TT + jA]) : -1e30f;
        float p0B = act ? (fb[jB] + tr[START_TAG * TT + jB]) : -1e30f;
        float mx = fmaxf(p0A, p0B);
        #pragma unroll
        for (int o = 16; o; o >>= 1)
            mx = fmaxf(mx, __shfl_xor_sync(0xffffffffu, mx, o));
        const float m0 = mx;
        uA = act ? ex2((p0A - m0) * LOG2E) : 0.0f;
        uB = act ? ex2((p0B - m0) * LOG2E) : 0.0f;
        ((float2*)shq[0])[t] = make_float2(uA, uB);
        __syncwarp();

        // emission pair prefetch (distance 4), pre-scaled by log2e
        const float2* pe = (const float2*)fb + tcl;   // stride 26 float2/step
        ull fl0 = 0, fl1 = 0, fl2 = 0, fl3 = 0;
        if (1 < L) { float2 v = pe[1 * 26]; fl0 = f2mul(f2pack(v.x, v.y), L2E2); }
        if (2 < L) { float2 v = pe[2 * 26]; fl1 = f2mul(f2pack(v.x, v.y), L2E2); }
        if (3 < L) { float2 v = pe[3 * 26]; fl2 = f2mul(f2pack(v.x, v.y), L2E2); }
        if (4 < L) { float2 v = pe[4 * 26]; fl3 = f2mul(f2pack(v.x, v.y), L2E2); }

#define FSTEP(SRC, DST) {                                                     \
        float2 fc = f2unpack(fl0);                                            \
        float efA = ex2(fc.x), efB = ex2(fc.y);                               \
        fl0 = fl1; fl1 = fl2; fl2 = fl3;                                      \
        int sp = s + 4;                                                       \
        float2 nv = make_float2(0.f, 0.f);                                    \
        if (sp < L) nv = pe[sp * 26];                                         \
        fl3 = f2mul(f2pack(nv.x, nv.y), L2E2);                                \
        const ulonglong2* q8 = (const ulonglong2*)shq[SRC];                   \
        ulonglong2 qv[13];                                                    \
        _Pragma("unroll") for (int c = 0; c < 13; c++) qv[c] = q8[c];         \
        float q0 = f2lo(qv[0].x);                                             \
        int exq = ((__float_as_int(q0) >> 23) & 0xFF) - 127;                  \
        Ktot += exq;                                                          \
        float scale = __int_as_float((127 - exq) << 23);                      \
        uA = matvec25(qv, EpA) * (scale * efA);                               \
        uB = matvec25(qv, EpB) * (scale * efB);                               \
        float2 st = act ? make_float2(uA, uB) : make_float2(0.f, 0.f);        \
        ((float2*)shq[DST])[t] = st;                                          \
        __syncwarp();                                                         \
        s++;                                                                  \
    }
        int s = 1;
        while (s + 1 < L) { FSTEP(0, 1) FSTEP(1, 0) }
        if (s < L) { FSTEP(0, 1) }
#undef FSTEP
        if (act) ((float2*)g_alpha[b])[t] = make_float2(uA, uB);
        if (t == 0) { g_Ka[b] = Ktot; g_m0[b] = m0; }
    } else {
        const int N = len - 1 - m;        // iterations: s = len-2 .. m
        // E rows jA, jB (contiguous 8B loads)
        ull EpA[25], EpB[25];
        const ull* ErA = (const ull*)(g_E + jA * TT);
        const ull* ErB = (const ull*)(g_E + jB * TT);
        #pragma unroll
        for (int c = 0; c < 25; c++) { EpA[c] = ErA[c]; EpB[c] = ErB[c]; }

        float EendA = g_E[jA * TT + END_TAG];
        float EendB = g_E[jB * TT + END_TAG];
        if (len >= 2) {
            const float* fl = fb + (size_t)(len - 1) * TT;
            uA = ex2(fl[jA] * LOG2E) * EendA;
            uB = ex2(fl[jB] * LOG2E) * EendB;
        } else {
            uA = EendA; uB = EendB;       // len==1: beta = E[:,END], no ef
        }
        if (!act) { uA = 0.f; uB = 0.f; }
        ((float2*)shq[0])[t] = make_float2(uA, uB);
        __syncwarp();

        // emission f_s needed only for iterations k <= N-2 (ef==1 at s==m)
        const float2* pb = (const float2*)fb + tcl;
        ull fl0 = 0, fl1 = 0, fl2 = 0, fl3 = 0;
        if (N >= 2) { float2 v = pb[(size_t)(len - 2) * 26]; fl0 = f2mul(f2pack(v.x, v.y), L2E2); }
        if (N >= 3) { float2 v = pb[(size_t)(len - 3) * 26]; fl1 = f2mul(f2pack(v.x, v.y), L2E2); }
        if (N >= 4) { float2 v = pb[(size_t)(len - 4) * 26]; fl2 = f2mul(f2pack(v.x, v.y), L2E2); }
        if (N >= 5) { float2 v = pb[(size_t)(len - 5) * 26]; fl3 = f2mul(f2pack(v.x, v.y), L2E2); }

#define BSTEP(SRC, DST) {                                                     \
        float2 fc = f2unpack(fl0);                                            \
        float efA = ex2(fc.x), efB = ex2(fc.y);                               \
        fl0 = fl1; fl1 = fl2; fl2 = fl3;                                      \
        int kk = k + 4;                                                       \
        float2 nv = make_float2(0.f, 0.f);                                    \
        if (kk <= N - 2) nv = pb[(size_t)(len - 2 - kk) * 26];                \
        fl3 = f2mul(f2pack(nv.x, nv.y), L2E2);                                \
        const ulonglong2* q8 = (const ulonglong2*)shq[SRC];                   \
        ulonglong2 qv[13];                                                    \
        _Pragma("unroll") for (int c = 0; c < 13; c++) qv[c] = q8[c];         \
        float q0 = f2lo(qv[0].x);                                             \
        int exq = ((__float_as_int(q0) >> 23) & 0xFF) - 127;                  \
        Ktot += exq;                                                          \
        float scale = __int_as_float((127 - exq) << 23);                      \
        uA = matvec25(qv, EpA) * (scale * efA);                               \
        uB = matvec25(qv, EpB) * (scale * efB);                               \
        float2 st = act ? make_float2(uA, uB) : make_float2(0.f, 0.f);        \
        ((float2*)shq[DST])[t] = st;                                          \
        __syncwarp();                                                         \
        k++;                                                                  \
    }
        int k = 0;
        while (k + 1 < N) { BSTEP(0, 1) BSTEP(1, 0) }
        if (k < N) { BSTEP(0, 1) }
#undef BSTEP
        if (act) ((float2*)g_beta[b])[t] = make_float2(uA, uB);
        if (t == 0) g_Kb[b] = Ktot;
    }
}

// ---------------- combine: logZ_b - gold_b ----------------
__global__ void k_combine() {
    int b = blockIdx.x;
    int l = threadIdx.x;   // 32
    double d = (double)g_alpha[b][l] * (double)g_beta[b][l];
    if (l < 18)
        d += (double)g_alpha[b][l + 32] * (double)g_beta[b][l + 32];
    #pragma unroll
    for (int o = 16; o; o >>= 1) d += __shfl_xor_sync(0xffffffffu, d, o);
    if (l == 0) {
        double gold = g_goldp[b][0] + g_goldp[b][1]
                    + g_goldp[b][2] + g_goldp[b][3];
        double logZ = (double)g_m0[b] +
                      (double)(g_Ka[b] + g_Kb[b]) * LN2 + log(d);
        g_final[b] = logZ - gold;
    }
}

// ---------------- final reduction ----------------
__global__ void k_reduce(float* out) {
    __shared__ double sh[16];
    int tid = threadIdx.x;  // 512 threads
    double a = g_final[tid];
    #pragma unroll
    for (int o = 16; o; o >>= 1) a += __shfl_xor_sync(0xffffffffu, a, o);
    if ((tid & 31) == 0) sh[tid >> 5] = a;
    __syncthreads();
    if (tid < 32) {
        double v = (tid < 16) ? sh[tid] : 0.0;
        #pragma unroll
        for (int o = 8; o; o >>= 1) v += __shfl_xor_sync(0xffffffffu, v, o);
        if (tid == 0) out[0] = (float)v;
    }
}

// ---------------- launch (fork-join: gold2 overlaps k_main) ----------------
extern "C" void kernel_launch(void* const* d_in, const int* in_sizes, int n_in,
                              void* d_out, int out_size) {
    const float* feats = (const float*)d_in[0];
    const void*  mask  = d_in[1];
    const int*   tags  = (const int*)d_in[2];
    const float* tr    = (const float*)d_in[3];
    float* out = (float*)d_out;

    cudaStream_t s2 = 0;
    cudaEvent_t evA = 0, evB = 0;
    bool forked =
        (cudaStreamCreateWithFlags(&s2, cudaStreamNonBlocking) == cudaSuccess) &&
        (cudaEventCreateWithFlags(&evA, cudaEventDisableTiming) == cudaSuccess) &&
        (cudaEventCreateWithFlags(&evB, cudaEventDisableTiming) == cudaSuccess);

    k_detect<<<1, 256>>>(mask, tr);
    k_len<<<4 * BB, 256>>>(mask);
    k_rank<<<1, BB>>>();

    if (forked) {
        cudaEventRecord(evA, 0);
        cudaStreamWaitEvent(s2, evA, 0);
        k_gold2<<<4 * BB, 256, 0, s2>>>(mask, feats, tags, tr);
        k_main<<<2 * BB, 32>>>(feats, tr);
        cudaEventRecord(evB, s2);
        cudaStreamWaitEvent(0, evB, 0);
    } else {
        k_gold2<<<4 * BB, 256>>>(mask, feats, tags, tr);
        k_main<<<2 * BB, 32>>>(feats, tr);
    }

    k_combine<<<BB, 32>>>();
    k_reduce<<<1, 512>>>(out);

    if (forked) {
        cudaEventDestroy(evA);
        cudaEventDestroy(evB);
        cudaStreamDestroy(s2);
    }
}